// round 14
// baseline (speedup 1.0000x reference)
#include <cuda_runtime.h>
#include <cuda_bf16.h>
#include <cstdint>

#define NN   50000
#define EE   800000
#define INF  128
#define HF   128
#define RR   8
#define OUTF 2
#define BN_EPS 1e-5f
#define GEMM_TILES ((NN + 127) / 128)   // 391 (BM=128)
#define BINS (RR * NN)                  // 400000 (type,src) bins
#define SCAN_BLOCKS ((BINS + 1023) / 1024)  // 391

// ---------------- scratch (device globals; no allocation allowed) ----------
__device__ float g_xw[(size_t)3 * NN * HF];         // 3 recycled xw slots (77MB, L2-resident)
__device__ float g_agg[(size_t)NN * HF];            // pre-BN layer output
__device__ __nv_bfloat16 g_xhi[(size_t)NN * HF];    // bf16 hi split of acts
__device__ __nv_bfloat16 g_xlo[(size_t)NN * HF];    // bf16 lo split
__device__ __nv_bfloat16 g_whi[9 * 128 * 128];      // [mat][n][k] W^T, hi
__device__ __nv_bfloat16 g_wlo[9 * 128 * 128];      // lo
__device__ int   g_deg[NN * RR];
__device__ float g_invdeg[NN * RR];
__device__ float g_sum[HF];
__device__ float g_sumsq[HF];
// edge sorting by (type, src)
__device__ int   g_hist[BINS];      // per-bin counts
__device__ int   g_hcur[BINS];      // scan result -> cursors (end after place)
__device__ int   g_bsum[SCAN_BLOCKS];
__device__ int   g_etgt[EE];        // targets, sorted by (type, src)

// ======================= small helpers ======================================
__device__ __forceinline__ uint32_t smem_to_u32(const void* p) {
    uint32_t a;
    asm("{ .reg .u64 t; cvta.to.shared.u64 t, %1; cvt.u32.u64 %0, t; }"
        : "=r"(a) : "l"(p));
    return a;
}
__device__ __forceinline__ void cp16(uint32_t dst, const void* src) {
    asm volatile("cp.async.cg.shared.global [%0], [%1], 16;"
                 :: "r"(dst), "l"(__cvta_generic_to_global(src)));
}
__device__ __forceinline__ void mma_bf16(float d[4], const uint32_t a[4],
                                         uint32_t b0, uint32_t b1) {
    asm volatile(
        "mma.sync.aligned.m16n8k16.row.col.f32.bf16.bf16.f32 "
        "{%0,%1,%2,%3}, {%4,%5,%6,%7}, {%8,%9}, {%0,%1,%2,%3};"
        : "+f"(d[0]), "+f"(d[1]), "+f"(d[2]), "+f"(d[3])
        : "r"(a[0]), "r"(a[1]), "r"(a[2]), "r"(a[3]), "r"(b0), "r"(b1));
}
__device__ __forceinline__ void ldsm_x4(uint32_t r[4], uint32_t addr) {
    asm volatile("ldmatrix.sync.aligned.m8n8.x4.shared.b16 {%0,%1,%2,%3}, [%4];"
        : "=r"(r[0]), "=r"(r[1]), "=r"(r[2]), "=r"(r[3]) : "r"(addr));
}

// =============== SMEM layout (u32 units), stride 68 u32 = 136 bf16 ==========
#define SWU    68
#define ROWB   (SWU * 4)                   // 272 bytes per row
#define AH_U   0
#define AL_U   (128 * SWU)                 // 8704
#define B0_U   (2 * 128 * SWU)             // 17408
#define B1_U   (B0_U + 128 * SWU)          // 26112
#define SMEM_U32S   (B1_U + 128 * SWU)     // 34816
#define SMEM_BYTES  (SMEM_U32S * 4)        // 139264  (R9 config)

// prefetch one 128x128 bf16 tile (row-major [n][k]) into padded smem
__device__ __forceinline__ void prefetch_B(uint32_t sb, int bofs_u,
                                           const __nv_bfloat16* W) {
    int tid = threadIdx.x;
#pragma unroll
    for (int i = 0; i < 8; i++) {
        int e = i * 256 + tid;            // 0..2047 uint4s
        int row = e >> 4;                 // 0..127
        int q   = e & 15;                 // uint4 (8 bf16) within row
        cp16(sb + (uint32_t)(bofs_u + row * SWU + q * 4) * 4, W + row * 128 + q * 8);
    }
}

// one bf16 pass via ldmatrix: D += A x B^T over K=128 (warp tile 64x32)
__device__ __forceinline__ void do_pass(uint32_t aBase, uint32_t bBase,
                                        uint32_t aLane, uint32_t bLane,
                                        float d[4][4][4]) {
#pragma unroll
    for (int ks = 0; ks < 8; ks++) {
        uint32_t kb = (uint32_t)ks * 32;          // 16 bf16 = 32 bytes
        uint32_t a[4][4];
#pragma unroll
        for (int mt = 0; mt < 4; mt++)
            ldsm_x4(a[mt], aBase + aLane + (uint32_t)(mt * 16) * ROWB + kb);
#pragma unroll
        for (int p = 0; p < 2; p++) {
            uint32_t b[4];
            ldsm_x4(b, bBase + bLane + (uint32_t)(p * 16) * ROWB + kb);
#pragma unroll
            for (int mt = 0; mt < 4; mt++) {
                mma_bf16(d[mt][2 * p],     a[mt], b[0], b[1]);
                mma_bf16(d[mt][2 * p + 1], a[mt], b[2], b[3]);
            }
        }
    }
}

// load A hi/lo tiles (128 rows) into smem, zero-padded past NN
__device__ __forceinline__ void load_A(uint32_t sb, uint32_t* smu, int m0) {
    int tid = threadIdx.x;
#pragma unroll
    for (int i = 0; i < 8; i++) {
        int e = i * 256 + tid;
        int row = e >> 4, q = e & 15;
        uint32_t dh = sb + (uint32_t)(AH_U + row * SWU + q * 4) * 4;
        uint32_t dl = sb + (uint32_t)(AL_U + row * SWU + q * 4) * 4;
        if (m0 + row < NN) {
            cp16(dh, g_xhi + (size_t)(m0 + row) * 128 + q * 8);
            cp16(dl, g_xlo + (size_t)(m0 + row) * 128 + q * 8);
        } else {
            uint4 z = make_uint4(0, 0, 0, 0);
            *reinterpret_cast<uint4*>(smu + AH_U + row * SWU + q * 4) = z;
            *reinterpret_cast<uint4*>(smu + AL_U + row * SWU + q * 4) = z;
        }
    }
}

// ============== bf16 tensor GEMM over a chunk of mats [mat0, mat0+nmats) =====
// mat == 8 -> g_agg (+bias); else -> xw slot (mat - mat0). R9 pipeline.
__global__ void __launch_bounds__(256, 1) gemm_tc_kernel(const float* __restrict__ bias,
                                                         int mat0, int nmats) {
    extern __shared__ uint32_t smu[];
    uint32_t sb = smem_to_u32(smu);
    const int tid = threadIdx.x;
    const int wid = tid >> 5, lane = tid & 31;
    const int wm = wid & 1, wn = wid >> 1;       // 2 x 4 warp grid (64x32 tiles)
    const int lr = lane >> 2, lc = lane & 3;
    const int m0 = blockIdx.x * 128;

    const uint32_t aLane = (uint32_t)(wm * 64 + (lane & 15)) * ROWB
                         + (uint32_t)(lane >> 4) * 16;
    const uint32_t bLane = (uint32_t)(wn * 32 + ((lane >> 4) & 1) * 8 + (lane & 7)) * ROWB
                         + (uint32_t)((lane >> 3) & 1) * 16;

    load_A(sb, smu, m0);
    prefetch_B(sb, B0_U, g_whi + mat0 * 16384);   // B_hi(first mat)
    asm volatile("cp.async.commit_group;" ::: "memory");
    asm volatile("cp.async.wait_group 0;" ::: "memory");
    __syncthreads();

    float d[4][4][4];
#pragma unroll
    for (int mt = 0; mt < 4; mt++)
#pragma unroll
        for (int nt = 0; nt < 4; nt++)
#pragma unroll
            for (int j = 0; j < 4; j++) d[mt][nt][j] = 0.f;

    const uint32_t ahB = sb + AH_U * 4;
    const uint32_t alB = sb + AL_U * 4;
    int stage = 0;
    const int ntiles = 2 * nmats;
    // even t = B_hi(mat0 + t/2) [Ahi & Alo passes], odd t = B_lo [Ahi pass]
    for (int t = 0; t < ntiles; t++) {
        if (t + 1 < ntiles) {
            int nm = mat0 + ((t + 1) >> 1);
            const __nv_bfloat16* Wn =
                ((t + 1) & 1) ? (g_wlo + nm * 16384) : (g_whi + nm * 16384);
            prefetch_B(sb, stage ? B0_U : B1_U, Wn);
        }
        asm volatile("cp.async.commit_group;" ::: "memory");

        const uint32_t bB = sb + (stage ? B1_U : B0_U) * 4;
        do_pass(ahB, bB, aLane, bLane, d);               // a_hi x b
        if (!(t & 1)) do_pass(alB, bB, aLane, bLane, d); // a_lo x b_hi

        if (t & 1) {
            int mat = mat0 + (t >> 1);
            float* gbase = (mat == 8) ? g_agg
                                      : (g_xw + (size_t)(mat - mat0) * NN * HF);
#pragma unroll
            for (int mt = 0; mt < 4; mt++) {
                int r0 = m0 + wm * 64 + mt * 16 + lr;
#pragma unroll
                for (int nt = 0; nt < 4; nt++) {
                    int col = wn * 32 + nt * 8 + lc * 2;
                    float b0 = 0.f, b1 = 0.f;
                    if (mat == 8) { b0 = bias[col]; b1 = bias[col + 1]; }
                    if (r0 < NN)
                        *reinterpret_cast<float2*>(gbase + (size_t)r0 * HF + col) =
                            make_float2(d[mt][nt][0] + b0, d[mt][nt][1] + b1);
                    if (r0 + 8 < NN)
                        *reinterpret_cast<float2*>(gbase + (size_t)(r0 + 8) * HF + col) =
                            make_float2(d[mt][nt][2] + b0, d[mt][nt][3] + b1);
#pragma unroll
                    for (int j = 0; j < 4; j++) d[mt][nt][j] = 0.f;
                }
            }
        }
        asm volatile("cp.async.wait_group 0;" ::: "memory");
        __syncthreads();
        stage ^= 1;
    }
}

// ======================= prep kernels ========================================
__global__ void split_x_kernel(const float* __restrict__ x_in) {
    size_t idx = (size_t)blockIdx.x * blockDim.x + threadIdx.x;
    if (idx >= (size_t)NN * HF) return;
    float v = x_in[idx];
    __nv_bfloat16 h = __float2bfloat16_rn(v);
    g_xhi[idx] = h;
    g_xlo[idx] = __float2bfloat16_rn(v - __bfloat162float(h));
}

// transpose W[mat][k][n] -> [mat][n][k], split hi/lo bf16. mat 8 = root.
__global__ void split_w_kernel(const float* __restrict__ w, const float* __restrict__ root) {
    int idx = blockIdx.x * blockDim.x + threadIdx.x;
    if (idx >= 9 * 16384) return;
    int mat = idx >> 14;
    int n = (idx >> 7) & 127;
    int k = idx & 127;
    float v = (mat < 8) ? w[(mat << 14) + (k << 7) + n] : root[(k << 7) + n];
    __nv_bfloat16 h = __float2bfloat16_rn(v);
    g_whi[idx] = h;
    g_wlo[idx] = __float2bfloat16_rn(v - __bfloat162float(h));
}

__global__ void zero_prep_kernel() {
    int idx = blockIdx.x * blockDim.x + threadIdx.x;
    if (idx < NN * RR) g_deg[idx] = 0;
    if (idx < BINS) g_hist[idx] = 0;
    if (idx < HF) { g_sum[idx] = 0.f; g_sumsq[idx] = 0.f; }
}
__global__ void zero_sums_kernel() {
    int idx = threadIdx.x;
    if (idx < HF) { g_sum[idx] = 0.f; g_sumsq[idx] = 0.f; }
}
__global__ void deg_hist_kernel(const int* __restrict__ ei, const int* __restrict__ et) {
    int e = blockIdx.x * blockDim.x + threadIdx.x;
    if (e >= EE) return;
    int src = ei[e];
    int tgt = ei[EE + e];
    int t   = et[e];
    atomicAdd(&g_deg[tgt * RR + t], 1);
    atomicAdd(&g_hist[t * NN + src], 1);
}
// per-1024-bin block sums (+ fused inv-degree LUT)
__global__ void scan1_kernel() {
    __shared__ int sh[256];
    int base = blockIdx.x * 1024;
    int t = threadIdx.x;
    int s = 0;
#pragma unroll
    for (int j = 0; j < 4; j++) {
        int idx = base + t * 4 + j;
        if (idx < BINS) {
            s += g_hist[idx];
            int dg = g_deg[idx];
            g_invdeg[idx] = (dg > 0) ? 1.0f / (float)dg : 0.f;
        }
    }
    sh[t] = s;
    __syncthreads();
    for (int off = 128; off > 0; off >>= 1) {
        if (t < off) sh[t] += sh[t + off];
        __syncthreads();
    }
    if (t == 0) g_bsum[blockIdx.x] = sh[0];
}
// per-block exclusive scan + self-computed block offset -> g_hcur
__global__ void scan3_kernel() {
    __shared__ int sh[256];
    __shared__ int offs;
    int t = threadIdx.x;
    int part = 0;
    for (int i = t; i < blockIdx.x; i += 256) part += g_bsum[i];
    sh[t] = part;
    __syncthreads();
    for (int off = 128; off > 0; off >>= 1) {
        if (t < off) sh[t] += sh[t + off];
        __syncthreads();
    }
    if (t == 0) offs = sh[0];
    __syncthreads();

    int base = blockIdx.x * 1024;
    int loc[4];
    int s = 0;
#pragma unroll
    for (int j = 0; j < 4; j++) {
        int idx = base + t * 4 + j;
        loc[j] = s;
        s += (idx < BINS) ? g_hist[idx] : 0;
    }
    sh[t] = s;
    __syncthreads();
    for (int off = 1; off < 256; off <<= 1) {
        int v = (t >= off) ? sh[t - off] : 0;
        __syncthreads();
        sh[t] += v;
        __syncthreads();
    }
    int texc = sh[t] - s + offs;
#pragma unroll
    for (int j = 0; j < 4; j++) {
        int idx = base + t * 4 + j;
        if (idx < BINS) g_hcur[idx] = texc + loc[j];
    }
}
__global__ void place_kernel(const int* __restrict__ ei, const int* __restrict__ et) {
    int e = blockIdx.x * blockDim.x + threadIdx.x;
    if (e >= EE) return;
    int src = ei[e];
    int tgt = ei[EE + e];
    int t   = et[e];
    int pos = atomicAdd(&g_hcur[t * NN + src], 1);
    g_etgt[pos] = tgt;
}

// --- bin scatter over rels [rel0, rel0+nrels): warp per (rel,src) bin --------
// xw slot for rel r is (r - rel0); bb = slot*NN + src indexes g_xw directly.
__global__ void scatter_kernel(int rel0, int nbins) {
    int bb = (blockIdx.x * blockDim.x + threadIdx.x) >> 5;
    if (bb >= nbins) return;
    int gbin = rel0 * NN + bb;          // global (type,src) bin
    int cnt = g_hist[gbin];
    if (cnt == 0) return;
    int lane = threadIdx.x & 31;
    int end   = g_hcur[gbin];
    int start = end - cnt;
    int rel = rel0 + bb / NN;
    float4 v = *reinterpret_cast<const float4*>(
        g_xw + (size_t)bb * HF + lane * 4);
    for (int i = start; i < end; i++) {
        int tgt = __ldg(&g_etgt[i]);
        float inv = __ldg(&g_invdeg[tgt * RR + rel]);
        float* dst = g_agg + (size_t)tgt * HF + lane * 4;
        asm volatile("red.global.add.v4.f32 [%0], {%1, %2, %3, %4};"
            :: "l"(__cvta_generic_to_global(dst)),
               "f"(v.x * inv), "f"(v.y * inv), "f"(v.z * inv), "f"(v.w * inv)
            : "memory");
    }
}

// ---------------- BN stats / apply ------------------------------------------
__global__ void bn_stats_kernel() {
    int c = threadIdx.x & 127;
    int rstart = blockIdx.x * (blockDim.x >> 7) + (threadIdx.x >> 7);
    int rstep  = gridDim.x * (blockDim.x >> 7);
    float s = 0.f, ss = 0.f;
    for (int r = rstart; r < NN; r += rstep) {
        float v = g_agg[(size_t)r * HF + c];
        s += v;
        ss += v * v;
    }
    atomicAdd(&g_sum[c], s);
    atomicAdd(&g_sumsq[c], ss);
}
__global__ void bn_apply_kernel(const float* __restrict__ gamma,
                                const float* __restrict__ beta) {
    int idx = blockIdx.x * blockDim.x + threadIdx.x;
    if (idx >= NN * HF) return;
    int c = idx & 127;
    const float invN = 1.0f / (float)NN;
    float mean = g_sum[c] * invN;
    float var  = fmaxf(g_sumsq[c] * invN - mean * mean, 0.f);
    float v = (g_agg[idx] - mean) * rsqrtf(var + BN_EPS) * gamma[c] + beta[c];
    v = fmaxf(v, 0.f);
    __nv_bfloat16 h = __float2bfloat16_rn(v);
    g_xhi[idx] = h;
    g_xlo[idx] = __float2bfloat16_rn(v - __bfloat162float(h));
}

// ---------------- classifier: out[N,2] = (hi+lo) @ cw + cb ------------------
__global__ void classifier_kernel(const float* __restrict__ cw,
                                  const float* __restrict__ cb,
                                  float* __restrict__ out) {
    __shared__ float wsm[HF * OUTF];
    if (threadIdx.x < HF * OUTF) wsm[threadIdx.x] = cw[threadIdx.x];
    __syncthreads();
    int w = (blockIdx.x * blockDim.x + threadIdx.x) >> 5;
    if (w >= NN) return;
    int lane = threadIdx.x & 31;
    const __nv_bfloat162* ph = reinterpret_cast<const __nv_bfloat162*>(
        g_xhi + (size_t)w * HF + lane * 4);
    const __nv_bfloat162* pl = reinterpret_cast<const __nv_bfloat162*>(
        g_xlo + (size_t)w * HF + lane * 4);
    __nv_bfloat162 h0 = ph[0], h1 = ph[1], l0 = pl[0], l1 = pl[1];
    float vx = __bfloat162float(h0.x) + __bfloat162float(l0.x);
    float vy = __bfloat162float(h0.y) + __bfloat162float(l0.y);
    float vz = __bfloat162float(h1.x) + __bfloat162float(l1.x);
    float vw = __bfloat162float(h1.y) + __bfloat162float(l1.y);
    int c = lane * 4;
    float o0 = vx * wsm[(c + 0) * 2]     + vy * wsm[(c + 1) * 2]
             + vz * wsm[(c + 2) * 2]     + vw * wsm[(c + 3) * 2];
    float o1 = vx * wsm[(c + 0) * 2 + 1] + vy * wsm[(c + 1) * 2 + 1]
             + vz * wsm[(c + 2) * 2 + 1] + vw * wsm[(c + 3) * 2 + 1];
#pragma unroll
    for (int off = 16; off > 0; off >>= 1) {
        o0 += __shfl_down_sync(0xFFFFFFFFu, o0, off);
        o1 += __shfl_down_sync(0xFFFFFFFFu, o1, off);
    }
    if (lane == 0) {
        out[(size_t)w * 2 + 0] = o0 + cb[0];
        out[(size_t)w * 2 + 1] = o1 + cb[1];
    }
}

// ================================ launch =====================================
extern "C" void kernel_launch(void* const* d_in, const int* in_sizes, int n_in,
                              void* d_out, int out_size) {
    const float* x    = (const float*)d_in[0];
    const int*   ei   = (const int*)d_in[1];
    const int*   et   = (const int*)d_in[2];
    const float* w1   = (const float*)d_in[3];
    const float* r1   = (const float*)d_in[4];
    const float* b1   = (const float*)d_in[5];
    const float* g1   = (const float*)d_in[6];
    const float* be1  = (const float*)d_in[7];
    const float* w2   = (const float*)d_in[8];
    const float* r2   = (const float*)d_in[9];
    const float* b2   = (const float*)d_in[10];
    const float* g2   = (const float*)d_in[11];
    const float* be2  = (const float*)d_in[12];
    const float* cw   = (const float*)d_in[13];
    const float* cb   = (const float*)d_in[14];
    float* out = (float*)d_out;

    cudaFuncSetAttribute(gemm_tc_kernel,
                         cudaFuncAttributeMaxDynamicSharedMemorySize, SMEM_BYTES);

    int bn_apply_blocks = (NN * HF + 255) / 256;
    int cls_blocks      = (NN * 32 + 255) / 256;
    int splitx_blocks   = (NN * HF + 255) / 256;
    int splitw_blocks   = (9 * 16384 + 255) / 256;
    int edge_blocks     = (EE + 255) / 256;
    int scat2 = (2 * NN * 32 + 255) / 256;     // 2-relation scatter grid
    int scat3 = (3 * NN * 32 + 255) / 256;     // 3-relation scatter grid

    // Chunk order: {6,7,8} first (root initializes agg), then {3,4,5}, {0,1,2}.
    // ncu captures the 4th kernel launch -> first GEMM chunk in slot 4.
    split_w_kernel<<<splitw_blocks, 256>>>(w1, r1);            // 1
    split_x_kernel<<<splitx_blocks, 256>>>(x);                 // 2
    zero_prep_kernel<<<(BINS + 255) / 256, 256>>>();           // 3
    gemm_tc_kernel<<<GEMM_TILES, 256, SMEM_BYTES>>>(b1, 6, 3); // 4 <- profiled
    deg_hist_kernel<<<edge_blocks, 256>>>(ei, et);             // 5
    scan1_kernel<<<SCAN_BLOCKS, 256>>>();                      // 6
    scan3_kernel<<<SCAN_BLOCKS, 256>>>();                      // 7
    place_kernel<<<edge_blocks, 256>>>(ei, et);                // 8
    scatter_kernel<<<scat2, 256>>>(6, 2 * NN);                 // rels 6-7
    gemm_tc_kernel<<<GEMM_TILES, 256, SMEM_BYTES>>>(b1, 3, 3);
    scatter_kernel<<<scat3, 256>>>(3, 3 * NN);                 // rels 3-5
    gemm_tc_kernel<<<GEMM_TILES, 256, SMEM_BYTES>>>(b1, 0, 3);
    scatter_kernel<<<scat3, 256>>>(0, 3 * NN);                 // rels 0-2
    bn_stats_kernel<<<256, 256>>>();
    bn_apply_kernel<<<bn_apply_blocks, 256>>>(g1, be1);

    // ---- layer 2 (degree + sorted edges reused) ----
    zero_sums_kernel<<<1, 128>>>();
    split_w_kernel<<<splitw_blocks, 256>>>(w2, r2);
    gemm_tc_kernel<<<GEMM_TILES, 256, SMEM_BYTES>>>(b2, 6, 3);
    scatter_kernel<<<scat2, 256>>>(6, 2 * NN);
    gemm_tc_kernel<<<GEMM_TILES, 256, SMEM_BYTES>>>(b2, 3, 3);
    scatter_kernel<<<scat3, 256>>>(3, 3 * NN);
    gemm_tc_kernel<<<GEMM_TILES, 256, SMEM_BYTES>>>(b2, 0, 3);
    scatter_kernel<<<scat3, 256>>>(0, 3 * NN);
    bn_stats_kernel<<<256, 256>>>();
    bn_apply_kernel<<<bn_apply_blocks, 256>>>(g2, be2);

    // ---- classifier ----
    classifier_kernel<<<cls_blocks, 256>>>(cw, cb, out);
}

// round 15
// speedup vs baseline: 1.1296x; 1.1296x over previous
#include <cuda_runtime.h>
#include <cuda_bf16.h>
#include <cstdint>

#define NN   50000
#define EE   800000
#define INF  128
#define HF   128
#define RR   8
#define OUTF 2
#define BN_EPS 1e-5f
#define GEMM_TILES ((NN + 127) / 128)   // 391 (BM=128)
#define BINS (RR * NN)                  // 400000 (type,src) bins
#define SCAN_BLOCKS ((BINS + 1023) / 1024)  // 391

// ---------------- scratch (device globals; no allocation allowed) ----------
__device__ float g_xw[(size_t)RR * NN * HF];        // [R][N][H] transformed
__device__ float g_agg[(size_t)NN * HF];            // pre-BN layer output
__device__ __nv_bfloat16 g_xhi[(size_t)NN * HF];    // bf16 hi split of acts
__device__ __nv_bfloat16 g_xlo[(size_t)NN * HF];    // bf16 lo split
__device__ __nv_bfloat16 g_whi[9 * 128 * 128];      // [mat][n][k] W^T, hi
__device__ __nv_bfloat16 g_wlo[9 * 128 * 128];      // lo
__device__ int   g_deg[NN * RR];
__device__ float g_invdeg[NN * RR];
__device__ float g_sum[HF];
__device__ float g_sumsq[HF];
// edge sorting by (type, src)
__device__ int   g_hist[BINS];      // per-bin counts
__device__ int   g_hcur[BINS];      // scan result -> cursors (end after place)
__device__ int   g_bsum[SCAN_BLOCKS];
__device__ int   g_etgt[EE];        // targets, sorted by (type, src)

// ======================= small helpers ======================================
__device__ __forceinline__ uint32_t smem_to_u32(const void* p) {
    uint32_t a;
    asm("{ .reg .u64 t; cvta.to.shared.u64 t, %1; cvt.u32.u64 %0, t; }"
        : "=r"(a) : "l"(p));
    return a;
}
__device__ __forceinline__ void cp16(uint32_t dst, const void* src) {
    asm volatile("cp.async.cg.shared.global [%0], [%1], 16;"
                 :: "r"(dst), "l"(__cvta_generic_to_global(src)));
}
__device__ __forceinline__ void mma_bf16(float d[4], const uint32_t a[4],
                                         uint32_t b0, uint32_t b1) {
    asm volatile(
        "mma.sync.aligned.m16n8k16.row.col.f32.bf16.bf16.f32 "
        "{%0,%1,%2,%3}, {%4,%5,%6,%7}, {%8,%9}, {%0,%1,%2,%3};"
        : "+f"(d[0]), "+f"(d[1]), "+f"(d[2]), "+f"(d[3])
        : "r"(a[0]), "r"(a[1]), "r"(a[2]), "r"(a[3]), "r"(b0), "r"(b1));
}
__device__ __forceinline__ void ldsm_x4(uint32_t r[4], uint32_t addr) {
    asm volatile("ldmatrix.sync.aligned.m8n8.x4.shared.b16 {%0,%1,%2,%3}, [%4];"
        : "=r"(r[0]), "=r"(r[1]), "=r"(r[2]), "=r"(r[3]) : "r"(addr));
}

// =============== SMEM layout =================================================
// A tiles: 128 rows x 128 bf16, stride 68 u32 (272 B).
// B half-tiles: 128 rows x 64 bf16, stride 36 u32 (144 B) -> rows 0..7 map to
// distinct 16B banks (144*r mod 128 = 16r), LDSM conflict-free.
#define SWU    68
#define ROWB   (SWU * 4)                   // 272 B (A row stride)
#define SWUB   36
#define ROWBB  (SWUB * 4)                  // 144 B (B half-tile row stride)
#define AH_U   0
#define AL_U   (128 * SWU)                 // 8704
#define B0_U   (2 * 128 * SWU)             // 17408
#define B1_U   (B0_U + 128 * SWUB)         // 22016
#define SMEM_U32S   (B1_U + 128 * SWUB)    // 26624
#define SMEM_BYTES  (SMEM_U32S * 4)        // 106496 -> 2 CTAs/SM

// prefetch one 128x64 bf16 B half-tile (row stride 128 bf16 in gmem)
__device__ __forceinline__ void prefetch_Bh(uint32_t sb, int bofs_u,
                                            const __nv_bfloat16* W) {
    int tid = threadIdx.x;
#pragma unroll
    for (int i = 0; i < 4; i++) {
        int e = i * 256 + tid;            // 0..1023 uint4s
        int row = e >> 3;                 // 0..127
        int q   = e & 7;                  // uint4 (8 bf16) within 64-bf16 row
        cp16(sb + (uint32_t)(bofs_u + row * SWUB + q * 4) * 4, W + row * 128 + q * 8);
    }
}

// half-K bf16 pass: D += A[:, koff..koff+64) x Bh^T (warp tile 64x32)
__device__ __forceinline__ void do_pass_h(uint32_t aBase, uint32_t bBase,
                                          uint32_t aLane, uint32_t bLane,
                                          uint32_t a_koff, float d[4][4][4]) {
#pragma unroll
    for (int ks = 0; ks < 4; ks++) {
        uint32_t kbA = a_koff + (uint32_t)ks * 32;   // 16 bf16 = 32 B
        uint32_t kbB = (uint32_t)ks * 32;
        uint32_t a[4][4];
#pragma unroll
        for (int mt = 0; mt < 4; mt++)
            ldsm_x4(a[mt], aBase + aLane + (uint32_t)(mt * 16) * ROWB + kbA);
#pragma unroll
        for (int p = 0; p < 2; p++) {
            uint32_t b[4];
            ldsm_x4(b, bBase + bLane + (uint32_t)(p * 16) * ROWBB + kbB);
#pragma unroll
            for (int mt = 0; mt < 4; mt++) {
                mma_bf16(d[mt][2 * p],     a[mt], b[0], b[1]);
                mma_bf16(d[mt][2 * p + 1], a[mt], b[2], b[3]);
            }
        }
    }
}

// load A hi/lo tiles (128 rows) into smem, zero-padded past NN
__device__ __forceinline__ void load_A(uint32_t sb, uint32_t* smu, int m0) {
    int tid = threadIdx.x;
#pragma unroll
    for (int i = 0; i < 8; i++) {
        int e = i * 256 + tid;
        int row = e >> 4, q = e & 15;
        uint32_t dh = sb + (uint32_t)(AH_U + row * SWU + q * 4) * 4;
        uint32_t dl = sb + (uint32_t)(AL_U + row * SWU + q * 4) * 4;
        if (m0 + row < NN) {
            cp16(dh, g_xhi + (size_t)(m0 + row) * 128 + q * 8);
            cp16(dl, g_xlo + (size_t)(m0 + row) * 128 + q * 8);
        } else {
            uint4 z = make_uint4(0, 0, 0, 0);
            *reinterpret_cast<uint4*>(smu + AH_U + row * SWU + q * 4) = z;
            *reinterpret_cast<uint4*>(smu + AL_U + row * SWU + q * 4) = z;
        }
    }
}

// gmem pointer for B half-tile t (t = mat*4 + sub; sub: 0=hi k0,1=hi k1,2=lo k0,3=lo k1)
__device__ __forceinline__ const __nv_bfloat16* btile_ptr(int t) {
    int mat = t >> 2, sub = t & 3;
    const __nv_bfloat16* base = (sub < 2) ? g_whi : g_wlo;
    return base + mat * 16384 + (sub & 1) * 64;
}

// ================== bf16 tensor GEMM: 9 matrices per 128-row M-tile =========
// 8 warps (2m x 4n), double-buffered half-K B tiles, 2 CTAs/SM.
__global__ void __launch_bounds__(256, 2) gemm_tc_kernel(const float* __restrict__ bias) {
    extern __shared__ uint32_t smu[];
    uint32_t sb = smem_to_u32(smu);
    const int tid = threadIdx.x;
    const int wid = tid >> 5, lane = tid & 31;
    const int wm = wid & 1, wn = wid >> 1;       // 2 x 4 warp grid (64x32 tiles)
    const int lr = lane >> 2, lc = lane & 3;
    const int m0 = blockIdx.x * 128;

    // A: row = wm*64 + (lane&15) (+mt*16), k-half-of-kstep = lane>>4
    const uint32_t aLane = (uint32_t)(wm * 64 + (lane & 15)) * ROWB
                         + (uint32_t)(lane >> 4) * 16;
    // B: n row = wn*32 + ((lane>>4)&1)*8 + (lane&7) (+p*16), k-half = (lane>>3)&1
    const uint32_t bLane = (uint32_t)(wn * 32 + ((lane >> 4) & 1) * 8 + (lane & 7)) * ROWBB
                         + (uint32_t)((lane >> 3) & 1) * 16;

    load_A(sb, smu, m0);
    prefetch_Bh(sb, B0_U, btile_ptr(0));
    asm volatile("cp.async.commit_group;" ::: "memory");
    asm volatile("cp.async.wait_group 0;" ::: "memory");
    __syncthreads();

    float d[4][4][4];
#pragma unroll
    for (int mt = 0; mt < 4; mt++)
#pragma unroll
        for (int nt = 0; nt < 4; nt++)
#pragma unroll
            for (int j = 0; j < 4; j++) d[mt][nt][j] = 0.f;

    const uint32_t ahB = sb + AH_U * 4;
    const uint32_t alB = sb + AL_U * 4;
    int stage = 0;
    // 36 half-tiles: t = mat*4 + sub. sub 0/1 (B_hi halves): Ahi+Alo passes.
    // sub 2/3 (B_lo halves): Ahi pass. Writeout after sub==3.
    for (int t = 0; t < 36; t++) {
        if (t + 1 < 36)
            prefetch_Bh(sb, stage ? B0_U : B1_U, btile_ptr(t + 1));
        asm volatile("cp.async.commit_group;" ::: "memory");

        const uint32_t bB = sb + (stage ? B1_U : B0_U) * 4;
        int sub = t & 3;
        uint32_t a_koff = (uint32_t)(sub & 1) * 128;   // 64 bf16 = 128 B
        do_pass_h(ahB, bB, aLane, bLane, a_koff, d);                 // a_hi x b
        if (sub < 2) do_pass_h(alB, bB, aLane, bLane, a_koff, d);    // a_lo x b_hi

        if (sub == 3) {
            int mat = t >> 2;
            float* gbase = (mat < 8) ? (g_xw + (size_t)mat * NN * HF) : g_agg;
#pragma unroll
            for (int mt = 0; mt < 4; mt++) {
                int r0 = m0 + wm * 64 + mt * 16 + lr;
#pragma unroll
                for (int nt = 0; nt < 4; nt++) {
                    int col = wn * 32 + nt * 8 + lc * 2;
                    float b0 = 0.f, b1 = 0.f;
                    if (mat == 8) { b0 = bias[col]; b1 = bias[col + 1]; }
                    if (r0 < NN)
                        *reinterpret_cast<float2*>(gbase + (size_t)r0 * HF + col) =
                            make_float2(d[mt][nt][0] + b0, d[mt][nt][1] + b1);
                    if (r0 + 8 < NN)
                        *reinterpret_cast<float2*>(gbase + (size_t)(r0 + 8) * HF + col) =
                            make_float2(d[mt][nt][2] + b0, d[mt][nt][3] + b1);
#pragma unroll
                    for (int j = 0; j < 4; j++) d[mt][nt][j] = 0.f;
                }
            }
        }
        asm volatile("cp.async.wait_group 0;" ::: "memory");
        __syncthreads();
        stage ^= 1;
    }
}

// ======================= prep kernels ========================================
__global__ void split_x_kernel(const float* __restrict__ x_in) {
    size_t idx = (size_t)blockIdx.x * blockDim.x + threadIdx.x;
    if (idx >= (size_t)NN * HF) return;
    float v = x_in[idx];
    __nv_bfloat16 h = __float2bfloat16_rn(v);
    g_xhi[idx] = h;
    g_xlo[idx] = __float2bfloat16_rn(v - __bfloat162float(h));
}

// transpose W[mat][k][n] -> [mat][n][k], split hi/lo bf16. mat 8 = root.
__global__ void split_w_kernel(const float* __restrict__ w, const float* __restrict__ root) {
    int idx = blockIdx.x * blockDim.x + threadIdx.x;
    if (idx >= 9 * 16384) return;
    int mat = idx >> 14;
    int n = (idx >> 7) & 127;
    int k = idx & 127;
    float v = (mat < 8) ? w[(mat << 14) + (k << 7) + n] : root[(k << 7) + n];
    __nv_bfloat16 h = __float2bfloat16_rn(v);
    g_whi[idx] = h;
    g_wlo[idx] = __float2bfloat16_rn(v - __bfloat162float(h));
}

__global__ void zero_prep_kernel() {
    int idx = blockIdx.x * blockDim.x + threadIdx.x;
    if (idx < NN * RR) g_deg[idx] = 0;
    if (idx < BINS) g_hist[idx] = 0;
    if (idx < HF) { g_sum[idx] = 0.f; g_sumsq[idx] = 0.f; }
}
__global__ void zero_sums_kernel() {
    int idx = threadIdx.x;
    if (idx < HF) { g_sum[idx] = 0.f; g_sumsq[idx] = 0.f; }
}
__global__ void deg_hist_kernel(const int* __restrict__ ei, const int* __restrict__ et) {
    int e = blockIdx.x * blockDim.x + threadIdx.x;
    if (e >= EE) return;
    int src = ei[e];
    int tgt = ei[EE + e];
    int t   = et[e];
    atomicAdd(&g_deg[tgt * RR + t], 1);
    atomicAdd(&g_hist[t * NN + src], 1);
}
// per-1024-bin block sums (+ fused inv-degree LUT)
__global__ void scan1_kernel() {
    __shared__ int sh[256];
    int base = blockIdx.x * 1024;
    int t = threadIdx.x;
    int s = 0;
#pragma unroll
    for (int j = 0; j < 4; j++) {
        int idx = base + t * 4 + j;
        if (idx < BINS) {
            s += g_hist[idx];
            int dg = g_deg[idx];
            g_invdeg[idx] = (dg > 0) ? 1.0f / (float)dg : 0.f;
        }
    }
    sh[t] = s;
    __syncthreads();
    for (int off = 128; off > 0; off >>= 1) {
        if (t < off) sh[t] += sh[t + off];
        __syncthreads();
    }
    if (t == 0) g_bsum[blockIdx.x] = sh[0];
}
// per-block exclusive scan + self-computed block offset -> g_hcur
__global__ void scan3_kernel() {
    __shared__ int sh[256];
    __shared__ int offs;
    int t = threadIdx.x;
    int part = 0;
    for (int i = t; i < blockIdx.x; i += 256) part += g_bsum[i];
    sh[t] = part;
    __syncthreads();
    for (int off = 128; off > 0; off >>= 1) {
        if (t < off) sh[t] += sh[t + off];
        __syncthreads();
    }
    if (t == 0) offs = sh[0];
    __syncthreads();

    int base = blockIdx.x * 1024;
    int loc[4];
    int s = 0;
#pragma unroll
    for (int j = 0; j < 4; j++) {
        int idx = base + t * 4 + j;
        loc[j] = s;
        s += (idx < BINS) ? g_hist[idx] : 0;
    }
    sh[t] = s;
    __syncthreads();
    for (int off = 1; off < 256; off <<= 1) {
        int v = (t >= off) ? sh[t - off] : 0;
        __syncthreads();
        sh[t] += v;
        __syncthreads();
    }
    int texc = sh[t] - s + offs;
#pragma unroll
    for (int j = 0; j < 4; j++) {
        int idx = base + t * 4 + j;
        if (idx < BINS) g_hcur[idx] = texc + loc[j];
    }
}
__global__ void place_kernel(const int* __restrict__ ei, const int* __restrict__ et) {
    int e = blockIdx.x * blockDim.x + threadIdx.x;
    if (e >= EE) return;
    int src = ei[e];
    int tgt = ei[EE + e];
    int t   = et[e];
    int pos = atomicAdd(&g_hcur[t * NN + src], 1);
    g_etgt[pos] = tgt;
}

// -------- bin scatter: one warp per (type,src) bin; gather once, red per tgt -
__global__ void scatter_kernel() {
    int b = (blockIdx.x * blockDim.x + threadIdx.x) >> 5;   // bin id
    if (b >= BINS) return;
    int cnt = g_hist[b];
    if (cnt == 0) return;
    int lane = threadIdx.x & 31;
    int end   = g_hcur[b];          // cursor advanced to bin end by place
    int start = end - cnt;
    int t   = b / NN;
    int src = b - t * NN;
    float4 v = *reinterpret_cast<const float4*>(
        g_xw + ((size_t)t * NN + src) * HF + lane * 4);
    for (int i = start; i < end; i++) {
        int tgt = __ldg(&g_etgt[i]);
        float inv = __ldg(&g_invdeg[tgt * RR + t]);
        float* dst = g_agg + (size_t)tgt * HF + lane * 4;
        asm volatile("red.global.add.v4.f32 [%0], {%1, %2, %3, %4};"
            :: "l"(__cvta_generic_to_global(dst)),
               "f"(v.x * inv), "f"(v.y * inv), "f"(v.z * inv), "f"(v.w * inv)
            : "memory");
    }
}

// ---------------- BN stats / apply ------------------------------------------
__global__ void bn_stats_kernel() {
    int c = threadIdx.x & 127;
    int rstart = blockIdx.x * (blockDim.x >> 7) + (threadIdx.x >> 7);
    int rstep  = gridDim.x * (blockDim.x >> 7);
    float s = 0.f, ss = 0.f;
    for (int r = rstart; r < NN; r += rstep) {
        float v = g_agg[(size_t)r * HF + c];
        s += v;
        ss += v * v;
    }
    atomicAdd(&g_sum[c], s);
    atomicAdd(&g_sumsq[c], ss);
}
__global__ void bn_apply_kernel(const float* __restrict__ gamma,
                                const float* __restrict__ beta) {
    int idx = blockIdx.x * blockDim.x + threadIdx.x;
    if (idx >= NN * HF) return;
    int c = idx & 127;
    const float invN = 1.0f / (float)NN;
    float mean = g_sum[c] * invN;
    float var  = fmaxf(g_sumsq[c] * invN - mean * mean, 0.f);
    float v = (g_agg[idx] - mean) * rsqrtf(var + BN_EPS) * gamma[c] + beta[c];
    v = fmaxf(v, 0.f);
    __nv_bfloat16 h = __float2bfloat16_rn(v);
    g_xhi[idx] = h;
    g_xlo[idx] = __float2bfloat16_rn(v - __bfloat162float(h));
}

// ---------------- classifier: out[N,2] = (hi+lo) @ cw + cb ------------------
__global__ void classifier_kernel(const float* __restrict__ cw,
                                  const float* __restrict__ cb,
                                  float* __restrict__ out) {
    __shared__ float wsm[HF * OUTF];
    if (threadIdx.x < HF * OUTF) wsm[threadIdx.x] = cw[threadIdx.x];
    __syncthreads();
    int w = (blockIdx.x * blockDim.x + threadIdx.x) >> 5;
    if (w >= NN) return;
    int lane = threadIdx.x & 31;
    const __nv_bfloat162* ph = reinterpret_cast<const __nv_bfloat162*>(
        g_xhi + (size_t)w * HF + lane * 4);
    const __nv_bfloat162* pl = reinterpret_cast<const __nv_bfloat162*>(
        g_xlo + (size_t)w * HF + lane * 4);
    __nv_bfloat162 h0 = ph[0], h1 = ph[1], l0 = pl[0], l1 = pl[1];
    float vx = __bfloat162float(h0.x) + __bfloat162float(l0.x);
    float vy = __bfloat162float(h0.y) + __bfloat162float(l0.y);
    float vz = __bfloat162float(h1.x) + __bfloat162float(l1.x);
    float vw = __bfloat162float(h1.y) + __bfloat162float(l1.y);
    int c = lane * 4;
    float o0 = vx * wsm[(c + 0) * 2]     + vy * wsm[(c + 1) * 2]
             + vz * wsm[(c + 2) * 2]     + vw * wsm[(c + 3) * 2];
    float o1 = vx * wsm[(c + 0) * 2 + 1] + vy * wsm[(c + 1) * 2 + 1]
             + vz * wsm[(c + 2) * 2 + 1] + vw * wsm[(c + 3) * 2 + 1];
#pragma unroll
    for (int off = 16; off > 0; off >>= 1) {
        o0 += __shfl_down_sync(0xFFFFFFFFu, o0, off);
        o1 += __shfl_down_sync(0xFFFFFFFFu, o1, off);
    }
    if (lane == 0) {
        out[(size_t)w * 2 + 0] = o0 + cb[0];
        out[(size_t)w * 2 + 1] = o1 + cb[1];
    }
}

// ================================ launch =====================================
extern "C" void kernel_launch(void* const* d_in, const int* in_sizes, int n_in,
                              void* d_out, int out_size) {
    const float* x    = (const float*)d_in[0];
    const int*   ei   = (const int*)d_in[1];
    const int*   et   = (const int*)d_in[2];
    const float* w1   = (const float*)d_in[3];
    const float* r1   = (const float*)d_in[4];
    const float* b1   = (const float*)d_in[5];
    const float* g1   = (const float*)d_in[6];
    const float* be1  = (const float*)d_in[7];
    const float* w2   = (const float*)d_in[8];
    const float* r2   = (const float*)d_in[9];
    const float* b2   = (const float*)d_in[10];
    const float* g2   = (const float*)d_in[11];
    const float* be2  = (const float*)d_in[12];
    const float* cw   = (const float*)d_in[13];
    const float* cb   = (const float*)d_in[14];
    float* out = (float*)d_out;

    cudaFuncSetAttribute(gemm_tc_kernel,
                         cudaFuncAttributeMaxDynamicSharedMemorySize, SMEM_BYTES);

    int scatter_blocks  = (BINS * 32 + 255) / 256;   // warp per bin
    int bn_apply_blocks = (NN * HF + 255) / 256;
    int cls_blocks      = (NN * 32 + 255) / 256;
    int splitx_blocks   = (NN * HF + 255) / 256;
    int splitw_blocks   = (9 * 16384 + 255) / 256;
    int edge_blocks     = (EE + 255) / 256;

    // ncu captures the 4th kernel launch -> GEMM stays in slot 4.
    split_w_kernel<<<splitw_blocks, 256>>>(w1, r1);            // 1
    split_x_kernel<<<splitx_blocks, 256>>>(x);                 // 2
    zero_prep_kernel<<<(BINS + 255) / 256, 256>>>();           // 3
    gemm_tc_kernel<<<GEMM_TILES, 256, SMEM_BYTES>>>(b1);       // 4 <- profiled
    deg_hist_kernel<<<edge_blocks, 256>>>(ei, et);             // 5
    scan1_kernel<<<SCAN_BLOCKS, 256>>>();                      // 6
    scan3_kernel<<<SCAN_BLOCKS, 256>>>();                      // 7
    place_kernel<<<edge_blocks, 256>>>(ei, et);                // 8
    scatter_kernel<<<scatter_blocks, 256>>>();                 // 9
    bn_stats_kernel<<<256, 256>>>();                           // 10
    bn_apply_kernel<<<bn_apply_blocks, 256>>>(g1, be1);        // 11

    // ---- layer 2 (degree + sorted edges reused) ----
    zero_sums_kernel<<<1, 128>>>();
    split_w_kernel<<<splitw_blocks, 256>>>(w2, r2);
    gemm_tc_kernel<<<GEMM_TILES, 256, SMEM_BYTES>>>(b2);
    scatter_kernel<<<scatter_blocks, 256>>>();
    bn_stats_kernel<<<256, 256>>>();
    bn_apply_kernel<<<bn_apply_blocks, 256>>>(g2, be2);

    // ---- classifier ----
    classifier_kernel<<<cls_blocks, 256>>>(cw, cb, out);
}

// round 16
// speedup vs baseline: 1.1522x; 1.0200x over previous
#include <cuda_runtime.h>
#include <cuda_bf16.h>
#include <cstdint>

#define NN   50000
#define EE   800000
#define INF  128
#define HF   128
#define RR   8
#define OUTF 2
#define BN_EPS 1e-5f
#define GEMM_TILES ((NN + 127) / 128)   // 391 (BM=128)
#define BINS (RR * NN)                  // 400000 (type,src) bins
#define SCAN_BLOCKS ((BINS + 1023) / 1024)  // 391

// ---------------- scratch (device globals; no allocation allowed) ----------
__device__ float g_xw[(size_t)RR * NN * HF];        // [R][N][H] transformed
__device__ float g_agg[(size_t)NN * HF];            // pre-BN layer output
__device__ __nv_bfloat16 g_xhi[(size_t)NN * HF];    // bf16 hi split of acts
__device__ __nv_bfloat16 g_xlo[(size_t)NN * HF];    // bf16 lo split
__device__ __nv_bfloat16 g_whi[9 * 128 * 128];      // [mat][n][k] W^T, hi
__device__ __nv_bfloat16 g_wlo[9 * 128 * 128];      // lo
__device__ int   g_deg[NN * RR];
__device__ float g_invdeg[NN * RR];
__device__ float g_sum[HF];
__device__ float g_sumsq[HF];
// edge sorting by (type, src)
__device__ int   g_hist[BINS];      // per-bin counts
__device__ int   g_hcur[BINS];      // scan result -> cursors (end after place)
__device__ int   g_bsum[SCAN_BLOCKS];
__device__ int   g_etgt[EE];        // targets, sorted by (type, src)

// ======================= small helpers ======================================
__device__ __forceinline__ uint32_t smem_to_u32(const void* p) {
    uint32_t a;
    asm("{ .reg .u64 t; cvta.to.shared.u64 t, %1; cvt.u32.u64 %0, t; }"
        : "=r"(a) : "l"(p));
    return a;
}
__device__ __forceinline__ void cp16(uint32_t dst, const void* src) {
    asm volatile("cp.async.cg.shared.global [%0], [%1], 16;"
                 :: "r"(dst), "l"(__cvta_generic_to_global(src)));
}
__device__ __forceinline__ void mma_bf16(float d[4], const uint32_t a[4],
                                         uint32_t b0, uint32_t b1) {
    asm volatile(
        "mma.sync.aligned.m16n8k16.row.col.f32.bf16.bf16.f32 "
        "{%0,%1,%2,%3}, {%4,%5,%6,%7}, {%8,%9}, {%0,%1,%2,%3};"
        : "+f"(d[0]), "+f"(d[1]), "+f"(d[2]), "+f"(d[3])
        : "r"(a[0]), "r"(a[1]), "r"(a[2]), "r"(a[3]), "r"(b0), "r"(b1));
}
__device__ __forceinline__ void ldsm_x4(uint32_t r[4], uint32_t addr) {
    asm volatile("ldmatrix.sync.aligned.m8n8.x4.shared.b16 {%0,%1,%2,%3}, [%4];"
        : "=r"(r[0]), "=r"(r[1]), "=r"(r[2]), "=r"(r[3]) : "r"(addr));
}

// =============== SMEM layout =================================================
// A tiles: 128 rows x 128 bf16, stride 68 u32 (272 B).
// B half-tiles: 128 rows x 64 bf16, stride 36 u32 (144 B) -> rows 0..7 map to
// distinct 16B banks (144*r mod 128 = 16r), LDSM conflict-free.
#define SWU    68
#define ROWB   (SWU * 4)                   // 272 B (A row stride)
#define SWUB   36
#define ROWBB  (SWUB * 4)                  // 144 B (B half-tile row stride)
#define AH_U   0
#define AL_U   (128 * SWU)                 // 8704
#define B0_U   (2 * 128 * SWU)             // 17408
#define B1_U   (B0_U + 128 * SWUB)         // 22016
#define SMEM_U32S   (B1_U + 128 * SWUB)    // 26624
#define SMEM_BYTES  (SMEM_U32S * 4)        // 106496 -> 2 CTAs/SM

// prefetch one 128x64 bf16 B half-tile (row stride 128 bf16 in gmem)
__device__ __forceinline__ void prefetch_Bh(uint32_t sb, int bofs_u,
                                            const __nv_bfloat16* W) {
    int tid = threadIdx.x;
#pragma unroll
    for (int i = 0; i < 4; i++) {
        int e = i * 256 + tid;            // 0..1023 uint4s
        int row = e >> 3;                 // 0..127
        int q   = e & 7;                  // uint4 (8 bf16) within 64-bf16 row
        cp16(sb + (uint32_t)(bofs_u + row * SWUB + q * 4) * 4, W + row * 128 + q * 8);
    }
}

// half-K bf16 pass: D += A[:, koff..koff+64) x Bh^T (warp tile 64x32)
__device__ __forceinline__ void do_pass_h(uint32_t aBase, uint32_t bBase,
                                          uint32_t aLane, uint32_t bLane,
                                          uint32_t a_koff, float d[4][4][4]) {
#pragma unroll
    for (int ks = 0; ks < 4; ks++) {
        uint32_t kbA = a_koff + (uint32_t)ks * 32;   // 16 bf16 = 32 B
        uint32_t kbB = (uint32_t)ks * 32;
        uint32_t a[4][4];
#pragma unroll
        for (int mt = 0; mt < 4; mt++)
            ldsm_x4(a[mt], aBase + aLane + (uint32_t)(mt * 16) * ROWB + kbA);
#pragma unroll
        for (int p = 0; p < 2; p++) {
            uint32_t b[4];
            ldsm_x4(b, bBase + bLane + (uint32_t)(p * 16) * ROWBB + kbB);
#pragma unroll
            for (int mt = 0; mt < 4; mt++) {
                mma_bf16(d[mt][2 * p],     a[mt], b[0], b[1]);
                mma_bf16(d[mt][2 * p + 1], a[mt], b[2], b[3]);
            }
        }
    }
}

// load A hi/lo tiles (128 rows) into smem, zero-padded past NN
__device__ __forceinline__ void load_A(uint32_t sb, uint32_t* smu, int m0) {
    int tid = threadIdx.x;
#pragma unroll
    for (int i = 0; i < 8; i++) {
        int e = i * 256 + tid;
        int row = e >> 4, q = e & 15;
        uint32_t dh = sb + (uint32_t)(AH_U + row * SWU + q * 4) * 4;
        uint32_t dl = sb + (uint32_t)(AL_U + row * SWU + q * 4) * 4;
        if (m0 + row < NN) {
            cp16(dh, g_xhi + (size_t)(m0 + row) * 128 + q * 8);
            cp16(dl, g_xlo + (size_t)(m0 + row) * 128 + q * 8);
        } else {
            uint4 z = make_uint4(0, 0, 0, 0);
            *reinterpret_cast<uint4*>(smu + AH_U + row * SWU + q * 4) = z;
            *reinterpret_cast<uint4*>(smu + AL_U + row * SWU + q * 4) = z;
        }
    }
}

// gmem pointer for B half-tile t (t = mat*4 + sub; sub: 0=hi k0,1=hi k1,2=lo k0,3=lo k1)
__device__ __forceinline__ const __nv_bfloat16* btile_ptr(int t) {
    int mat = t >> 2, sub = t & 3;
    const __nv_bfloat16* base = (sub < 2) ? g_whi : g_wlo;
    return base + mat * 16384 + (sub & 1) * 64;
}

// ================== bf16 tensor GEMM: 9 matrices per 128-row M-tile =========
// 8 warps (2m x 4n), double-buffered half-K B tiles, 2 CTAs/SM.
__global__ void __launch_bounds__(256, 2) gemm_tc_kernel(const float* __restrict__ bias) {
    extern __shared__ uint32_t smu[];
    uint32_t sb = smem_to_u32(smu);
    const int tid = threadIdx.x;
    const int wid = tid >> 5, lane = tid & 31;
    const int wm = wid & 1, wn = wid >> 1;       // 2 x 4 warp grid (64x32 tiles)
    const int lr = lane >> 2, lc = lane & 3;
    const int m0 = blockIdx.x * 128;

    const uint32_t aLane = (uint32_t)(wm * 64 + (lane & 15)) * ROWB
                         + (uint32_t)(lane >> 4) * 16;
    const uint32_t bLane = (uint32_t)(wn * 32 + ((lane >> 4) & 1) * 8 + (lane & 7)) * ROWBB
                         + (uint32_t)((lane >> 3) & 1) * 16;

    load_A(sb, smu, m0);
    prefetch_Bh(sb, B0_U, btile_ptr(0));
    asm volatile("cp.async.commit_group;" ::: "memory");
    asm volatile("cp.async.wait_group 0;" ::: "memory");
    __syncthreads();

    float d[4][4][4];
#pragma unroll
    for (int mt = 0; mt < 4; mt++)
#pragma unroll
        for (int nt = 0; nt < 4; nt++)
#pragma unroll
            for (int j = 0; j < 4; j++) d[mt][nt][j] = 0.f;

    const uint32_t ahB = sb + AH_U * 4;
    const uint32_t alB = sb + AL_U * 4;
    int stage = 0;
    // 36 half-tiles: t = mat*4 + sub. sub 0/1 (B_hi halves): Ahi+Alo passes.
    // sub 2/3 (B_lo halves): Ahi pass. Writeout after sub==3.
    for (int t = 0; t < 36; t++) {
        if (t + 1 < 36)
            prefetch_Bh(sb, stage ? B0_U : B1_U, btile_ptr(t + 1));
        asm volatile("cp.async.commit_group;" ::: "memory");

        const uint32_t bB = sb + (stage ? B1_U : B0_U) * 4;
        int sub = t & 3;
        uint32_t a_koff = (uint32_t)(sub & 1) * 128;   // 64 bf16 = 128 B
        do_pass_h(ahB, bB, aLane, bLane, a_koff, d);                 // a_hi x b
        if (sub < 2) do_pass_h(alB, bB, aLane, bLane, a_koff, d);    // a_lo x b_hi

        if (sub == 3) {
            int mat = t >> 2;
            float* gbase = (mat < 8) ? (g_xw + (size_t)mat * NN * HF) : g_agg;
#pragma unroll
            for (int mt = 0; mt < 4; mt++) {
                int r0 = m0 + wm * 64 + mt * 16 + lr;
#pragma unroll
                for (int nt = 0; nt < 4; nt++) {
                    int col = wn * 32 + nt * 8 + lc * 2;
                    float b0 = 0.f, b1 = 0.f;
                    if (mat == 8) { b0 = bias[col]; b1 = bias[col + 1]; }
                    if (r0 < NN)
                        *reinterpret_cast<float2*>(gbase + (size_t)r0 * HF + col) =
                            make_float2(d[mt][nt][0] + b0, d[mt][nt][1] + b1);
                    if (r0 + 8 < NN)
                        *reinterpret_cast<float2*>(gbase + (size_t)(r0 + 8) * HF + col) =
                            make_float2(d[mt][nt][2] + b0, d[mt][nt][3] + b1);
#pragma unroll
                    for (int j = 0; j < 4; j++) d[mt][nt][j] = 0.f;
                }
            }
        }
        asm volatile("cp.async.wait_group 0;" ::: "memory");
        __syncthreads();
        stage ^= 1;
    }
}

// ======================= prep kernels ========================================
__global__ void split_x_kernel(const float* __restrict__ x_in) {
    size_t idx = (size_t)blockIdx.x * blockDim.x + threadIdx.x;
    if (idx >= (size_t)NN * HF) return;
    float v = x_in[idx];
    __nv_bfloat16 h = __float2bfloat16_rn(v);
    g_xhi[idx] = h;
    g_xlo[idx] = __float2bfloat16_rn(v - __bfloat162float(h));
}

// transpose W[mat][k][n] -> [mat][n][k], split hi/lo bf16. mat 8 = root.
__global__ void split_w_kernel(const float* __restrict__ w, const float* __restrict__ root) {
    int idx = blockIdx.x * blockDim.x + threadIdx.x;
    if (idx >= 9 * 16384) return;
    int mat = idx >> 14;
    int n = (idx >> 7) & 127;
    int k = idx & 127;
    float v = (mat < 8) ? w[(mat << 14) + (k << 7) + n] : root[(k << 7) + n];
    __nv_bfloat16 h = __float2bfloat16_rn(v);
    g_whi[idx] = h;
    g_wlo[idx] = __float2bfloat16_rn(v - __bfloat162float(h));
}

__global__ void zero_prep_kernel() {
    int idx = blockIdx.x * blockDim.x + threadIdx.x;
    if (idx < NN * RR) g_deg[idx] = 0;
    if (idx < BINS) g_hist[idx] = 0;
    if (idx < HF) { g_sum[idx] = 0.f; g_sumsq[idx] = 0.f; }
}
__global__ void zero_sums_kernel() {
    int idx = threadIdx.x;
    if (idx < HF) { g_sum[idx] = 0.f; g_sumsq[idx] = 0.f; }
}
__global__ void deg_hist_kernel(const int* __restrict__ ei, const int* __restrict__ et) {
    int e = blockIdx.x * blockDim.x + threadIdx.x;
    if (e >= EE) return;
    int src = ei[e];
    int tgt = ei[EE + e];
    int t   = et[e];
    atomicAdd(&g_deg[tgt * RR + t], 1);
    atomicAdd(&g_hist[t * NN + src], 1);
}
// per-1024-bin block sums (+ fused inv-degree LUT)
__global__ void scan1_kernel() {
    __shared__ int sh[256];
    int base = blockIdx.x * 1024;
    int t = threadIdx.x;
    int s = 0;
#pragma unroll
    for (int j = 0; j < 4; j++) {
        int idx = base + t * 4 + j;
        if (idx < BINS) {
            s += g_hist[idx];
            int dg = g_deg[idx];
            g_invdeg[idx] = (dg > 0) ? 1.0f / (float)dg : 0.f;
        }
    }
    sh[t] = s;
    __syncthreads();
    for (int off = 128; off > 0; off >>= 1) {
        if (t < off) sh[t] += sh[t + off];
        __syncthreads();
    }
    if (t == 0) g_bsum[blockIdx.x] = sh[0];
}
// per-block exclusive scan + self-computed block offset -> g_hcur
__global__ void scan3_kernel() {
    __shared__ int sh[256];
    __shared__ int offs;
    int t = threadIdx.x;
    int part = 0;
    for (int i = t; i < blockIdx.x; i += 256) part += g_bsum[i];
    sh[t] = part;
    __syncthreads();
    for (int off = 128; off > 0; off >>= 1) {
        if (t < off) sh[t] += sh[t + off];
        __syncthreads();
    }
    if (t == 0) offs = sh[0];
    __syncthreads();

    int base = blockIdx.x * 1024;
    int loc[4];
    int s = 0;
#pragma unroll
    for (int j = 0; j < 4; j++) {
        int idx = base + t * 4 + j;
        loc[j] = s;
        s += (idx < BINS) ? g_hist[idx] : 0;
    }
    sh[t] = s;
    __syncthreads();
    for (int off = 1; off < 256; off <<= 1) {
        int v = (t >= off) ? sh[t - off] : 0;
        __syncthreads();
        sh[t] += v;
        __syncthreads();
    }
    int texc = sh[t] - s + offs;
#pragma unroll
    for (int j = 0; j < 4; j++) {
        int idx = base + t * 4 + j;
        if (idx < BINS) g_hcur[idx] = texc + loc[j];
    }
}
__global__ void place_kernel(const int* __restrict__ ei, const int* __restrict__ et) {
    int e = blockIdx.x * blockDim.x + threadIdx.x;
    if (e >= EE) return;
    int src = ei[e];
    int tgt = ei[EE + e];
    int t   = et[e];
    int pos = atomicAdd(&g_hcur[t * NN + src], 1);
    g_etgt[pos] = tgt;
}

// -------- bin scatter: one warp per (type,src) bin; gather once, red per tgt -
__global__ void scatter_kernel() {
    int b = (blockIdx.x * blockDim.x + threadIdx.x) >> 5;   // bin id
    if (b >= BINS) return;
    int cnt = g_hist[b];
    if (cnt == 0) return;
    int lane = threadIdx.x & 31;
    int end   = g_hcur[b];          // cursor advanced to bin end by place
    int start = end - cnt;
    int t   = b / NN;
    int src = b - t * NN;
    float4 v = *reinterpret_cast<const float4*>(
        g_xw + ((size_t)t * NN + src) * HF + lane * 4);
    for (int i = start; i < end; i++) {
        int tgt = __ldg(&g_etgt[i]);
        float inv = __ldg(&g_invdeg[tgt * RR + t]);
        float* dst = g_agg + (size_t)tgt * HF + lane * 4;
        asm volatile("red.global.add.v4.f32 [%0], {%1, %2, %3, %4};"
            :: "l"(__cvta_generic_to_global(dst)),
               "f"(v.x * inv), "f"(v.y * inv), "f"(v.z * inv), "f"(v.w * inv)
            : "memory");
    }
}

// ---------------- BN stats / apply ------------------------------------------
__global__ void bn_stats_kernel() {
    int c = threadIdx.x & 127;
    int rstart = blockIdx.x * (blockDim.x >> 7) + (threadIdx.x >> 7);
    int rstep  = gridDim.x * (blockDim.x >> 7);
    float s = 0.f, ss = 0.f;
    for (int r = rstart; r < NN; r += rstep) {
        float v = g_agg[(size_t)r * HF + c];
        s += v;
        ss += v * v;
    }
    atomicAdd(&g_sum[c], s);
    atomicAdd(&g_sumsq[c], ss);
}
__global__ void bn_apply_kernel(const float* __restrict__ gamma,
                                const float* __restrict__ beta) {
    int idx = blockIdx.x * blockDim.x + threadIdx.x;
    if (idx >= NN * HF) return;
    int c = idx & 127;
    const float invN = 1.0f / (float)NN;
    float mean = g_sum[c] * invN;
    float var  = fmaxf(g_sumsq[c] * invN - mean * mean, 0.f);
    float v = (g_agg[idx] - mean) * rsqrtf(var + BN_EPS) * gamma[c] + beta[c];
    v = fmaxf(v, 0.f);
    __nv_bfloat16 h = __float2bfloat16_rn(v);
    g_xhi[idx] = h;
    g_xlo[idx] = __float2bfloat16_rn(v - __bfloat162float(h));
}

// ---------------- classifier: out[N,2] = (hi+lo) @ cw + cb ------------------
__global__ void classifier_kernel(const float* __restrict__ cw,
                                  const float* __restrict__ cb,
                                  float* __restrict__ out) {
    __shared__ float wsm[HF * OUTF];
    if (threadIdx.x < HF * OUTF) wsm[threadIdx.x] = cw[threadIdx.x];
    __syncthreads();
    int w = (blockIdx.x * blockDim.x + threadIdx.x) >> 5;
    if (w >= NN) return;
    int lane = threadIdx.x & 31;
    const __nv_bfloat162* ph = reinterpret_cast<const __nv_bfloat162*>(
        g_xhi + (size_t)w * HF + lane * 4);
    const __nv_bfloat162* pl = reinterpret_cast<const __nv_bfloat162*>(
        g_xlo + (size_t)w * HF + lane * 4);
    __nv_bfloat162 h0 = ph[0], h1 = ph[1], l0 = pl[0], l1 = pl[1];
    float vx = __bfloat162float(h0.x) + __bfloat162float(l0.x);
    float vy = __bfloat162float(h0.y) + __bfloat162float(l0.y);
    float vz = __bfloat162float(h1.x) + __bfloat162float(l1.x);
    float vw = __bfloat162float(h1.y) + __bfloat162float(l1.y);
    int c = lane * 4;
    float o0 = vx * wsm[(c + 0) * 2]     + vy * wsm[(c + 1) * 2]
             + vz * wsm[(c + 2) * 2]     + vw * wsm[(c + 3) * 2];
    float o1 = vx * wsm[(c + 0) * 2 + 1] + vy * wsm[(c + 1) * 2 + 1]
             + vz * wsm[(c + 2) * 2 + 1] + vw * wsm[(c + 3) * 2 + 1];
#pragma unroll
    for (int off = 16; off > 0; off >>= 1) {
        o0 += __shfl_down_sync(0xFFFFFFFFu, o0, off);
        o1 += __shfl_down_sync(0xFFFFFFFFu, o1, off);
    }
    if (lane == 0) {
        out[(size_t)w * 2 + 0] = o0 + cb[0];
        out[(size_t)w * 2 + 1] = o1 + cb[1];
    }
}

// ================================ launch =====================================
// Two-stream overlap: prep chain runs on s_aux concurrent with layer-1 GEMM;
// split_w2 runs on s_aux concurrent with layer-1 scatter. Streams/events are
// lazily created on the first (non-captured) correctness call; event record/
// wait are graph-capturable ops that become graph edges.
static cudaStream_t s_aux = nullptr;
static cudaEvent_t ev_fork = nullptr, ev_prep = nullptr,
                   ev_g1 = nullptr, ev_w2 = nullptr;

extern "C" void kernel_launch(void* const* d_in, const int* in_sizes, int n_in,
                              void* d_out, int out_size) {
    const float* x    = (const float*)d_in[0];
    const int*   ei   = (const int*)d_in[1];
    const int*   et   = (const int*)d_in[2];
    const float* w1   = (const float*)d_in[3];
    const float* r1   = (const float*)d_in[4];
    const float* b1   = (const float*)d_in[5];
    const float* g1   = (const float*)d_in[6];
    const float* be1  = (const float*)d_in[7];
    const float* w2   = (const float*)d_in[8];
    const float* r2   = (const float*)d_in[9];
    const float* b2   = (const float*)d_in[10];
    const float* g2   = (const float*)d_in[11];
    const float* be2  = (const float*)d_in[12];
    const float* cw   = (const float*)d_in[13];
    const float* cb   = (const float*)d_in[14];
    float* out = (float*)d_out;

    if (s_aux == nullptr) {
        cudaStreamCreateWithFlags(&s_aux, cudaStreamNonBlocking);
        cudaEventCreateWithFlags(&ev_fork, cudaEventDisableTiming);
        cudaEventCreateWithFlags(&ev_prep, cudaEventDisableTiming);
        cudaEventCreateWithFlags(&ev_g1,   cudaEventDisableTiming);
        cudaEventCreateWithFlags(&ev_w2,   cudaEventDisableTiming);
    }

    cudaFuncSetAttribute(gemm_tc_kernel,
                         cudaFuncAttributeMaxDynamicSharedMemorySize, SMEM_BYTES);

    int scatter_blocks  = (BINS * 32 + 255) / 256;   // warp per bin
    int bn_apply_blocks = (NN * HF + 255) / 256;
    int cls_blocks      = (NN * 32 + 255) / 256;
    int splitx_blocks   = (NN * HF + 255) / 256;
    int splitw_blocks   = (9 * 16384 + 255) / 256;
    int edge_blocks     = (EE + 255) / 256;

    // ---- fork: prep chain on s_aux, GEMM path on main stream ----
    cudaEventRecord(ev_fork, 0);
    cudaStreamWaitEvent(s_aux, ev_fork, 0);

    split_w_kernel<<<splitw_blocks, 256>>>(w1, r1);                  // main #1
    split_x_kernel<<<splitx_blocks, 256>>>(x);                       // main #2
    zero_prep_kernel<<<(BINS + 255) / 256, 256, 0, s_aux>>>();       // aux  #3
    gemm_tc_kernel<<<GEMM_TILES, 256, SMEM_BYTES>>>(b1);             // main #4 <- profiled
    deg_hist_kernel<<<edge_blocks, 256, 0, s_aux>>>(ei, et);         // aux
    scan1_kernel<<<SCAN_BLOCKS, 256, 0, s_aux>>>();                  // aux
    scan3_kernel<<<SCAN_BLOCKS, 256, 0, s_aux>>>();                  // aux
    place_kernel<<<edge_blocks, 256, 0, s_aux>>>(ei, et);            // aux
    cudaEventRecord(ev_prep, s_aux);

    // split_w2 on aux, but only after gemm1 finished reading g_whi/g_wlo (WAR)
    cudaEventRecord(ev_g1, 0);
    cudaStreamWaitEvent(s_aux, ev_g1, 0);
    split_w_kernel<<<splitw_blocks, 256, 0, s_aux>>>(w2, r2);
    cudaEventRecord(ev_w2, s_aux);

    // ---- join: scatter needs gemm1 (same stream) + prep chain ----
    cudaStreamWaitEvent(0, ev_prep, 0);
    scatter_kernel<<<scatter_blocks, 256>>>();
    bn_stats_kernel<<<256, 256>>>();
    bn_apply_kernel<<<bn_apply_blocks, 256>>>(g1, be1);
    zero_sums_kernel<<<1, 128>>>();

    // ---- layer 2 (needs split_w2 from aux) ----
    cudaStreamWaitEvent(0, ev_w2, 0);
    gemm_tc_kernel<<<GEMM_TILES, 256, SMEM_BYTES>>>(b2);
    scatter_kernel<<<scatter_blocks, 256>>>();
    bn_stats_kernel<<<256, 256>>>();
    bn_apply_kernel<<<bn_apply_blocks, 256>>>(g2, be2);

    // ---- classifier ----
    classifier_kernel<<<cls_blocks, 256>>>(cw, cb, out);
}

// round 17
// speedup vs baseline: 1.3150x; 1.1413x over previous
#include <cuda_runtime.h>
#include <cuda_fp16.h>
#include <cstdint>

#define NN   50000
#define EE   800000
#define INF  128
#define HF   128
#define RR   8
#define OUTF 2
#define BN_EPS 1e-5f
#define GEMM_TILES ((NN + 127) / 128)   // 391 (BM=128)
#define BINS (RR * NN)                  // 400000 (type,src) bins
#define SCAN_BLOCKS ((BINS + 1023) / 1024)  // 391

// ---------------- scratch (device globals; no allocation allowed) ----------
__device__ float g_xw[(size_t)RR * NN * HF];        // [R][N][H] transformed
__device__ float g_agg[(size_t)NN * HF];            // pre-BN layer output
__device__ __half g_xhi[(size_t)NN * HF];           // fp16 hi split of acts
__device__ __half g_xlo[(size_t)NN * HF];           // fp16 lo split
__device__ __half g_wh[9 * 128 * 128];              // [mat][n][k] W^T, fp16
__device__ int   g_deg[NN * RR];
__device__ float g_invdeg[NN * RR];
__device__ float g_sum[HF];
__device__ float g_sumsq[HF];
// edge sorting by (type, src)
__device__ int   g_hist[BINS];
__device__ int   g_hcur[BINS];
__device__ int   g_bsum[SCAN_BLOCKS];
__device__ int   g_etgt[EE];

// ======================= small helpers ======================================
__device__ __forceinline__ uint32_t smem_to_u32(const void* p) {
    uint32_t a;
    asm("{ .reg .u64 t; cvta.to.shared.u64 t, %1; cvt.u32.u64 %0, t; }"
        : "=r"(a) : "l"(p));
    return a;
}
__device__ __forceinline__ void cp16(uint32_t dst, const void* src) {
    asm volatile("cp.async.cg.shared.global [%0], [%1], 16;"
                 :: "r"(dst), "l"(__cvta_generic_to_global(src)));
}
__device__ __forceinline__ void mma_f16(float d[4], const uint32_t a[4],
                                        uint32_t b0, uint32_t b1) {
    asm volatile(
        "mma.sync.aligned.m16n8k16.row.col.f32.f16.f16.f32 "
        "{%0,%1,%2,%3}, {%4,%5,%6,%7}, {%8,%9}, {%0,%1,%2,%3};"
        : "+f"(d[0]), "+f"(d[1]), "+f"(d[2]), "+f"(d[3])
        : "r"(a[0]), "r"(a[1]), "r"(a[2]), "r"(a[3]), "r"(b0), "r"(b1));
}
__device__ __forceinline__ void ldsm_x4(uint32_t r[4], uint32_t addr) {
    asm volatile("ldmatrix.sync.aligned.m8n8.x4.shared.b16 {%0,%1,%2,%3}, [%4];"
        : "=r"(r[0]), "=r"(r[1]), "=r"(r[2]), "=r"(r[3]) : "r"(addr));
}

// =============== SMEM layout =================================================
// A tiles: 128 rows x 128 fp16, stride 68 u32 (272 B).
// B half-tiles: 128 rows x 64 fp16, stride 36 u32 (144 B) -> conflict-free LDSM.
#define SWU    68
#define ROWB   (SWU * 4)                   // 272 B (A row stride)
#define SWUB   36
#define ROWBB  (SWUB * 4)                  // 144 B (B half-tile row stride)
#define AH_U   0
#define AL_U   (128 * SWU)                 // 8704
#define B0_U   (2 * 128 * SWU)             // 17408
#define B1_U   (B0_U + 128 * SWUB)         // 22016
#define SMEM_U32S   (B1_U + 128 * SWUB)    // 26624
#define SMEM_BYTES  (SMEM_U32S * 4)        // 106496 -> 2 CTAs/SM

// prefetch one 128x64 fp16 B half-tile (row stride 128 fp16 in gmem)
__device__ __forceinline__ void prefetch_Bh(uint32_t sb, int bofs_u,
                                            const __half* W) {
    int tid = threadIdx.x;
#pragma unroll
    for (int i = 0; i < 4; i++) {
        int e = i * 256 + tid;            // 0..1023 uint4s
        int row = e >> 3;                 // 0..127
        int q   = e & 7;                  // uint4 (8 fp16) within 64-fp16 row
        cp16(sb + (uint32_t)(bofs_u + row * SWUB + q * 4) * 4, W + row * 128 + q * 8);
    }
}

// half-K fp16 pass: D += A[:, koff..koff+64) x Bh^T (warp tile 64x32)
__device__ __forceinline__ void do_pass_h(uint32_t aBase, uint32_t bBase,
                                          uint32_t aLane, uint32_t bLane,
                                          uint32_t a_koff, float d[4][4][4]) {
#pragma unroll
    for (int ks = 0; ks < 4; ks++) {
        uint32_t kbA = a_koff + (uint32_t)ks * 32;   // 16 fp16 = 32 B
        uint32_t kbB = (uint32_t)ks * 32;
        uint32_t a[4][4];
#pragma unroll
        for (int mt = 0; mt < 4; mt++)
            ldsm_x4(a[mt], aBase + aLane + (uint32_t)(mt * 16) * ROWB + kbA);
#pragma unroll
        for (int p = 0; p < 2; p++) {
            uint32_t b[4];
            ldsm_x4(b, bBase + bLane + (uint32_t)(p * 16) * ROWBB + kbB);
#pragma unroll
            for (int mt = 0; mt < 4; mt++) {
                mma_f16(d[mt][2 * p],     a[mt], b[0], b[1]);
                mma_f16(d[mt][2 * p + 1], a[mt], b[2], b[3]);
            }
        }
    }
}

// load A hi/lo tiles (128 rows) into smem, zero-padded past NN
__device__ __forceinline__ void load_A(uint32_t sb, uint32_t* smu, int m0) {
    int tid = threadIdx.x;
#pragma unroll
    for (int i = 0; i < 8; i++) {
        int e = i * 256 + tid;
        int row = e >> 4, q = e & 15;
        uint32_t dh = sb + (uint32_t)(AH_U + row * SWU + q * 4) * 4;
        uint32_t dl = sb + (uint32_t)(AL_U + row * SWU + q * 4) * 4;
        if (m0 + row < NN) {
            cp16(dh, g_xhi + (size_t)(m0 + row) * 128 + q * 8);
            cp16(dl, g_xlo + (size_t)(m0 + row) * 128 + q * 8);
        } else {
            uint4 z = make_uint4(0, 0, 0, 0);
            *reinterpret_cast<uint4*>(smu + AH_U + row * SWU + q * 4) = z;
            *reinterpret_cast<uint4*>(smu + AL_U + row * SWU + q * 4) = z;
        }
    }
}

// gmem pointer for B half-tile t (t = mat*2 + sub; sub: 0 = k0..63, 1 = k64..127)
__device__ __forceinline__ const __half* btile_ptr(int t) {
    int mat = t >> 1, sub = t & 1;
    return g_wh + mat * 16384 + sub * 64;
}

// ================== fp16 tensor GEMM: 9 matrices per 128-row M-tile =========
// 8 warps (2m x 4n), double-buffered half-K B tiles, 2 CTAs/SM.
// D = (a_hi + a_lo) x b_fp16 : 2 passes per half-tile.
__global__ void __launch_bounds__(256, 2) gemm_tc_kernel(const float* __restrict__ bias) {
    extern __shared__ uint32_t smu[];
    uint32_t sb = smem_to_u32(smu);
    const int tid = threadIdx.x;
    const int wid = tid >> 5, lane = tid & 31;
    const int wm = wid & 1, wn = wid >> 1;       // 2 x 4 warp grid (64x32 tiles)
    const int lr = lane >> 2, lc = lane & 3;
    const int m0 = blockIdx.x * 128;

    const uint32_t aLane = (uint32_t)(wm * 64 + (lane & 15)) * ROWB
                         + (uint32_t)(lane >> 4) * 16;
    const uint32_t bLane = (uint32_t)(wn * 32 + ((lane >> 4) & 1) * 8 + (lane & 7)) * ROWBB
                         + (uint32_t)((lane >> 3) & 1) * 16;

    load_A(sb, smu, m0);
    prefetch_Bh(sb, B0_U, btile_ptr(0));
    asm volatile("cp.async.commit_group;" ::: "memory");
    asm volatile("cp.async.wait_group 0;" ::: "memory");
    __syncthreads();

    float d[4][4][4];
#pragma unroll
    for (int mt = 0; mt < 4; mt++)
#pragma unroll
        for (int nt = 0; nt < 4; nt++)
#pragma unroll
            for (int j = 0; j < 4; j++) d[mt][nt][j] = 0.f;

    const uint32_t ahB = sb + AH_U * 4;
    const uint32_t alB = sb + AL_U * 4;
    int stage = 0;
    // 18 half-tiles: t = mat*2 + sub. Each: a_hi and a_lo passes. Writeout @ sub==1.
    for (int t = 0; t < 18; t++) {
        if (t + 1 < 18)
            prefetch_Bh(sb, stage ? B0_U : B1_U, btile_ptr(t + 1));
        asm volatile("cp.async.commit_group;" ::: "memory");

        const uint32_t bB = sb + (stage ? B1_U : B0_U) * 4;
        int sub = t & 1;
        uint32_t a_koff = (uint32_t)sub * 128;   // 64 fp16 = 128 B
        do_pass_h(ahB, bB, aLane, bLane, a_koff, d);   // a_hi x b
        do_pass_h(alB, bB, aLane, bLane, a_koff, d);   // a_lo x b

        if (sub == 1) {
            int mat = t >> 1;
            float* gbase = (mat < 8) ? (g_xw + (size_t)mat * NN * HF) : g_agg;
#pragma unroll
            for (int mt = 0; mt < 4; mt++) {
                int r0 = m0 + wm * 64 + mt * 16 + lr;
#pragma unroll
                for (int nt = 0; nt < 4; nt++) {
                    int col = wn * 32 + nt * 8 + lc * 2;
                    float b0 = 0.f, b1 = 0.f;
                    if (mat == 8) { b0 = bias[col]; b1 = bias[col + 1]; }
                    if (r0 < NN)
                        *reinterpret_cast<float2*>(gbase + (size_t)r0 * HF + col) =
                            make_float2(d[mt][nt][0] + b0, d[mt][nt][1] + b1);
                    if (r0 + 8 < NN)
                        *reinterpret_cast<float2*>(gbase + (size_t)(r0 + 8) * HF + col) =
                            make_float2(d[mt][nt][2] + b0, d[mt][nt][3] + b1);
#pragma unroll
                    for (int j = 0; j < 4; j++) d[mt][nt][j] = 0.f;
                }
            }
        }
        asm volatile("cp.async.wait_group 0;" ::: "memory");
        __syncthreads();
        stage ^= 1;
    }
}

// ======================= prep kernels ========================================
__global__ void split_x_kernel(const float* __restrict__ x_in) {
    size_t idx = (size_t)blockIdx.x * blockDim.x + threadIdx.x;
    if (idx >= (size_t)NN * HF) return;
    float v = x_in[idx];
    __half h = __float2half_rn(v);
    g_xhi[idx] = h;
    g_xlo[idx] = __float2half_rn(v - __half2float(h));
}

// transpose W[mat][k][n] -> [mat][n][k], round to fp16. mat 8 = root.
__global__ void split_w_kernel(const float* __restrict__ w, const float* __restrict__ root) {
    int idx = blockIdx.x * blockDim.x + threadIdx.x;
    if (idx >= 9 * 16384) return;
    int mat = idx >> 14;
    int n = (idx >> 7) & 127;
    int k = idx & 127;
    float v = (mat < 8) ? w[(mat << 14) + (k << 7) + n] : root[(k << 7) + n];
    g_wh[idx] = __float2half_rn(v);
}

__global__ void zero_prep_kernel() {
    int idx = blockIdx.x * blockDim.x + threadIdx.x;
    if (idx < NN * RR) g_deg[idx] = 0;
    if (idx < BINS) g_hist[idx] = 0;
    if (idx < HF) { g_sum[idx] = 0.f; g_sumsq[idx] = 0.f; }
}
__global__ void zero_sums_kernel() {
    int idx = threadIdx.x;
    if (idx < HF) { g_sum[idx] = 0.f; g_sumsq[idx] = 0.f; }
}
__global__ void deg_hist_kernel(const int* __restrict__ ei, const int* __restrict__ et) {
    int e = blockIdx.x * blockDim.x + threadIdx.x;
    if (e >= EE) return;
    int src = ei[e];
    int tgt = ei[EE + e];
    int t   = et[e];
    atomicAdd(&g_deg[tgt * RR + t], 1);
    atomicAdd(&g_hist[t * NN + src], 1);
}
__global__ void scan1_kernel() {
    __shared__ int sh[256];
    int base = blockIdx.x * 1024;
    int t = threadIdx.x;
    int s = 0;
#pragma unroll
    for (int j = 0; j < 4; j++) {
        int idx = base + t * 4 + j;
        if (idx < BINS) {
            s += g_hist[idx];
            int dg = g_deg[idx];
            g_invdeg[idx] = (dg > 0) ? 1.0f / (float)dg : 0.f;
        }
    }
    sh[t] = s;
    __syncthreads();
    for (int off = 128; off > 0; off >>= 1) {
        if (t < off) sh[t] += sh[t + off];
        __syncthreads();
    }
    if (t == 0) g_bsum[blockIdx.x] = sh[0];
}
__global__ void scan3_kernel() {
    __shared__ int sh[256];
    __shared__ int offs;
    int t = threadIdx.x;
    int part = 0;
    for (int i = t; i < blockIdx.x; i += 256) part += g_bsum[i];
    sh[t] = part;
    __syncthreads();
    for (int off = 128; off > 0; off >>= 1) {
        if (t < off) sh[t] += sh[t + off];
        __syncthreads();
    }
    if (t == 0) offs = sh[0];
    __syncthreads();

    int base = blockIdx.x * 1024;
    int loc[4];
    int s = 0;
#pragma unroll
    for (int j = 0; j < 4; j++) {
        int idx = base + t * 4 + j;
        loc[j] = s;
        s += (idx < BINS) ? g_hist[idx] : 0;
    }
    sh[t] = s;
    __syncthreads();
    for (int off = 1; off < 256; off <<= 1) {
        int v = (t >= off) ? sh[t - off] : 0;
        __syncthreads();
        sh[t] += v;
        __syncthreads();
    }
    int texc = sh[t] - s + offs;
#pragma unroll
    for (int j = 0; j < 4; j++) {
        int idx = base + t * 4 + j;
        if (idx < BINS) g_hcur[idx] = texc + loc[j];
    }
}
__global__ void place_kernel(const int* __restrict__ ei, const int* __restrict__ et) {
    int e = blockIdx.x * blockDim.x + threadIdx.x;
    if (e >= EE) return;
    int src = ei[e];
    int tgt = ei[EE + e];
    int t   = et[e];
    int pos = atomicAdd(&g_hcur[t * NN + src], 1);
    g_etgt[pos] = tgt;
}

// -------- bin scatter: one warp per (type,src) bin; gather once, red per tgt -
__global__ void scatter_kernel() {
    int b = (blockIdx.x * blockDim.x + threadIdx.x) >> 5;
    if (b >= BINS) return;
    int cnt = g_hist[b];
    if (cnt == 0) return;
    int lane = threadIdx.x & 31;
    int end   = g_hcur[b];
    int start = end - cnt;
    int t   = b / NN;
    int src = b - t * NN;
    float4 v = *reinterpret_cast<const float4*>(
        g_xw + ((size_t)t * NN + src) * HF + lane * 4);
    for (int i = start; i < end; i++) {
        int tgt = __ldg(&g_etgt[i]);
        float inv = __ldg(&g_invdeg[tgt * RR + t]);
        float* dst = g_agg + (size_t)tgt * HF + lane * 4;
        asm volatile("red.global.add.v4.f32 [%0], {%1, %2, %3, %4};"
            :: "l"(__cvta_generic_to_global(dst)),
               "f"(v.x * inv), "f"(v.y * inv), "f"(v.z * inv), "f"(v.w * inv)
            : "memory");
    }
}

// ---------------- BN stats / apply ------------------------------------------
__global__ void bn_stats_kernel() {
    int c = threadIdx.x & 127;
    int rstart = blockIdx.x * (blockDim.x >> 7) + (threadIdx.x >> 7);
    int rstep  = gridDim.x * (blockDim.x >> 7);
    float s = 0.f, ss = 0.f;
    for (int r = rstart; r < NN; r += rstep) {
        float v = g_agg[(size_t)r * HF + c];
        s += v;
        ss += v * v;
    }
    atomicAdd(&g_sum[c], s);
    atomicAdd(&g_sumsq[c], ss);
}
__global__ void bn_apply_kernel(const float* __restrict__ gamma,
                                const float* __restrict__ beta) {
    int idx = blockIdx.x * blockDim.x + threadIdx.x;
    if (idx >= NN * HF) return;
    int c = idx & 127;
    const float invN = 1.0f / (float)NN;
    float mean = g_sum[c] * invN;
    float var  = fmaxf(g_sumsq[c] * invN - mean * mean, 0.f);
    float v = (g_agg[idx] - mean) * rsqrtf(var + BN_EPS) * gamma[c] + beta[c];
    v = fmaxf(v, 0.f);
    __half h = __float2half_rn(v);
    g_xhi[idx] = h;
    g_xlo[idx] = __float2half_rn(v - __half2float(h));
}

// ---------------- classifier: out[N,2] = (hi+lo) @ cw + cb ------------------
__global__ void classifier_kernel(const float* __restrict__ cw,
                                  const float* __restrict__ cb,
                                  float* __restrict__ out) {
    __shared__ float wsm[HF * OUTF];
    if (threadIdx.x < HF * OUTF) wsm[threadIdx.x] = cw[threadIdx.x];
    __syncthreads();
    int w = (blockIdx.x * blockDim.x + threadIdx.x) >> 5;
    if (w >= NN) return;
    int lane = threadIdx.x & 31;
    const __half2* ph = reinterpret_cast<const __half2*>(
        g_xhi + (size_t)w * HF + lane * 4);
    const __half2* pl = reinterpret_cast<const __half2*>(
        g_xlo + (size_t)w * HF + lane * 4);
    __half2 h0 = ph[0], h1 = ph[1], l0 = pl[0], l1 = pl[1];
    float vx = __half2float(h0.x) + __half2float(l0.x);
    float vy = __half2float(h0.y) + __half2float(l0.y);
    float vz = __half2float(h1.x) + __half2float(l1.x);
    float vw = __half2float(h1.y) + __half2float(l1.y);
    int c = lane * 4;
    float o0 = vx * wsm[(c + 0) * 2]     + vy * wsm[(c + 1) * 2]
             + vz * wsm[(c + 2) * 2]     + vw * wsm[(c + 3) * 2];
    float o1 = vx * wsm[(c + 0) * 2 + 1] + vy * wsm[(c + 1) * 2 + 1]
             + vz * wsm[(c + 2) * 2 + 1] + vw * wsm[(c + 3) * 2 + 1];
#pragma unroll
    for (int off = 16; off > 0; off >>= 1) {
        o0 += __shfl_down_sync(0xFFFFFFFFu, o0, off);
        o1 += __shfl_down_sync(0xFFFFFFFFu, o1, off);
    }
    if (lane == 0) {
        out[(size_t)w * 2 + 0] = o0 + cb[0];
        out[(size_t)w * 2 + 1] = o1 + cb[1];
    }
}

// ================================ launch =====================================
// Two-stream overlap: prep chain on s_aux concurrent with layer-1 GEMM;
// split_w2 on s_aux concurrent with layer-1 scatter.
static cudaStream_t s_aux = nullptr;
static cudaEvent_t ev_fork = nullptr, ev_prep = nullptr,
                   ev_g1 = nullptr, ev_w2 = nullptr;

extern "C" void kernel_launch(void* const* d_in, const int* in_sizes, int n_in,
                              void* d_out, int out_size) {
    const float* x    = (const float*)d_in[0];
    const int*   ei   = (const int*)d_in[1];
    const int*   et   = (const int*)d_in[2];
    const float* w1   = (const float*)d_in[3];
    const float* r1   = (const float*)d_in[4];
    const float* b1   = (const float*)d_in[5];
    const float* g1   = (const float*)d_in[6];
    const float* be1  = (const float*)d_in[7];
    const float* w2   = (const float*)d_in[8];
    const float* r2   = (const float*)d_in[9];
    const float* b2   = (const float*)d_in[10];
    const float* g2   = (const float*)d_in[11];
    const float* be2  = (const float*)d_in[12];
    const float* cw   = (const float*)d_in[13];
    const float* cb   = (const float*)d_in[14];
    float* out = (float*)d_out;

    if (s_aux == nullptr) {
        cudaStreamCreateWithFlags(&s_aux, cudaStreamNonBlocking);
        cudaEventCreateWithFlags(&ev_fork, cudaEventDisableTiming);
        cudaEventCreateWithFlags(&ev_prep, cudaEventDisableTiming);
        cudaEventCreateWithFlags(&ev_g1,   cudaEventDisableTiming);
        cudaEventCreateWithFlags(&ev_w2,   cudaEventDisableTiming);
    }

    cudaFuncSetAttribute(gemm_tc_kernel,
                         cudaFuncAttributeMaxDynamicSharedMemorySize, SMEM_BYTES);

    int scatter_blocks  = (BINS * 32 + 255) / 256;
    int bn_apply_blocks = (NN * HF + 255) / 256;
    int cls_blocks      = (NN * 32 + 255) / 256;
    int splitx_blocks   = (NN * HF + 255) / 256;
    int splitw_blocks   = (9 * 16384 + 255) / 256;
    int edge_blocks     = (EE + 255) / 256;

    // ---- fork: prep chain on s_aux, GEMM path on main stream ----
    cudaEventRecord(ev_fork, 0);
    cudaStreamWaitEvent(s_aux, ev_fork, 0);

    split_w_kernel<<<splitw_blocks, 256>>>(w1, r1);
    split_x_kernel<<<splitx_blocks, 256>>>(x);
    zero_prep_kernel<<<(BINS + 255) / 256, 256, 0, s_aux>>>();
    gemm_tc_kernel<<<GEMM_TILES, 256, SMEM_BYTES>>>(b1);
    deg_hist_kernel<<<edge_blocks, 256, 0, s_aux>>>(ei, et);
    scan1_kernel<<<SCAN_BLOCKS, 256, 0, s_aux>>>();
    scan3_kernel<<<SCAN_BLOCKS, 256, 0, s_aux>>>();
    place_kernel<<<edge_blocks, 256, 0, s_aux>>>(ei, et);
    cudaEventRecord(ev_prep, s_aux);

    // split_w2 on aux, after gemm1 finished reading g_wh (WAR)
    cudaEventRecord(ev_g1, 0);
    cudaStreamWaitEvent(s_aux, ev_g1, 0);
    split_w_kernel<<<splitw_blocks, 256, 0, s_aux>>>(w2, r2);
    cudaEventRecord(ev_w2, s_aux);

    // ---- join: scatter needs gemm1 (same stream) + prep chain ----
    cudaStreamWaitEvent(0, ev_prep, 0);
    scatter_kernel<<<scatter_blocks, 256>>>();
    bn_stats_kernel<<<256, 256>>>();
    bn_apply_kernel<<<bn_apply_blocks, 256>>>(g1, be1);
    zero_sums_kernel<<<1, 128>>>();

    // ---- layer 2 (needs split_w2 from aux) ----
    cudaStreamWaitEvent(0, ev_w2, 0);
    gemm_tc_kernel<<<GEMM_TILES, 256, SMEM_BYTES>>>(b2);
    scatter_kernel<<<scatter_blocks, 256>>>();
    bn_stats_kernel<<<256, 256>>>();
    bn_apply_kernel<<<bn_apply_blocks, 256>>>(g2, be2);

    // ---- classifier ----
    classifier_kernel<<<cls_blocks, 256>>>(cw, cb, out);
}